// round 2
// baseline (speedup 1.0000x reference)
#include <cuda_runtime.h>
#include <cstdint>

// Problem dims (fixed by the dataset)
#define B_  128
#define T_  254
#define D_  768
#define H_  1024
#define M_  (B_ * T_)      // 32512  (divisible by 128)
#define K1_ (2 * D_)       // 1536
#define N1_ (2 * H_)       // 2048
#define K2_ N1_            // 2048
#define N2_ H_             // 1024

// Scratch (device globals — no allocation allowed in kernel_launch)
__device__ float g_feats[(size_t)M_ * K1_];  // [M, 1536]
__device__ float g_h1[(size_t)M_ * N1_];     // [M, 2048]
__device__ float g_h2[(size_t)M_ * N2_];     // [M, 1024]

// ---------------------------------------------------------------------------
// Kernel 1: exclusive prefix mean + copy -> feats = [prefix_mean | h]
// One thread per (b, d); serial scan over T. Fully coalesced in d.
// ---------------------------------------------------------------------------
__global__ void prefix_kernel(const float* __restrict__ h) {
    int idx = blockIdx.x * blockDim.x + threadIdx.x;
    if (idx >= B_ * D_) return;
    int b = idx / D_;
    int d = idx - b * D_;
    const float* hp = h + (size_t)b * T_ * D_ + d;
    size_t frow = (size_t)b * T_ * K1_ + d;
    float run = 0.0f;
    for (int t = 0; t < T_; ++t) {
        float x = hp[(size_t)t * D_];
        float cnt = (float)(t > 1 ? t : 1);
        g_feats[frow + (size_t)t * K1_]        = run / cnt;  // prefix mean (excl.)
        g_feats[frow + (size_t)t * K1_ + D_]   = x;          // current token
        run += x;
    }
}

// ---------------------------------------------------------------------------
// TF32 tensor-core GEMM: C = relu(A @ B + bias)
// A: [M,K] row-major fp32, B: [K,N] row-major fp32, C: [M,N] row-major.
// Block tile 128x128x32, 8 warps (4x2), warp tile 32x64, mma.sync m16n8k8.
// M, N, K assumed multiples of 128/128/32 (true for all our shapes).
// ---------------------------------------------------------------------------
#define BM 128
#define BN 128
#define BK 32
#define AS_STRIDE 36   // 36 mod 32 == 4  -> conflict-free A fragment LDS
#define BS_STRIDE 136  // 136 mod 32 == 8 -> conflict-free B fragment LDS

__device__ __forceinline__ uint32_t f2tf32(float x) {
    uint32_t r;
    asm("cvt.rna.tf32.f32 %0, %1;" : "=r"(r) : "f"(x));
    return r;
}

template <bool RELU>
__global__ __launch_bounds__(256) void gemm_tf32(
    const float* __restrict__ A, const float* __restrict__ Bm,
    const float* __restrict__ bias, float* __restrict__ C,
    int M, int N, int K)
{
    __shared__ uint32_t As[BM * AS_STRIDE];
    __shared__ uint32_t Bs[BK * BS_STRIDE];

    const int tid  = threadIdx.x;
    const int warp = tid >> 5;
    const int lane = tid & 31;
    const int wm = warp & 3;        // 4 warps along M
    const int wn = warp >> 2;       // 2 warps along N
    const int g  = lane >> 2;       // group id (0..7)
    const int tg = lane & 3;        // thread-in-group (0..3)

    const int bm = blockIdx.x * BM;
    const int bn = blockIdx.y * BN;

    float acc[2][8][4];
    #pragma unroll
    for (int i = 0; i < 2; ++i)
        #pragma unroll
        for (int j = 0; j < 8; ++j)
            #pragma unroll
            for (int c = 0; c < 4; ++c) acc[i][j][c] = 0.0f;

    for (int k0 = 0; k0 < K; k0 += BK) {
        // --- load A tile: 128 rows x 32 cols = 1024 float4 / 256 thr = 4 each
        #pragma unroll
        for (int i = 0; i < 4; ++i) {
            int idx = tid + i * 256;
            int r  = idx >> 3;            // row in tile
            int c4 = (idx & 7) << 2;      // col (float4 granularity)
            float4 v = *(const float4*)(A + (size_t)(bm + r) * K + k0 + c4);
            uint4 p;
            p.x = f2tf32(v.x); p.y = f2tf32(v.y);
            p.z = f2tf32(v.z); p.w = f2tf32(v.w);
            *(uint4*)&As[r * AS_STRIDE + c4] = p;
        }
        // --- load B tile: 32 rows x 128 cols = 1024 float4
        #pragma unroll
        for (int i = 0; i < 4; ++i) {
            int idx = tid + i * 256;
            int r  = idx >> 5;            // k row in tile
            int c4 = (idx & 31) << 2;     // n col
            float4 v = *(const float4*)(Bm + (size_t)(k0 + r) * N + bn + c4);
            uint4 p;
            p.x = f2tf32(v.x); p.y = f2tf32(v.y);
            p.z = f2tf32(v.z); p.w = f2tf32(v.w);
            *(uint4*)&Bs[r * BS_STRIDE + c4] = p;
        }
        __syncthreads();

        #pragma unroll
        for (int kk = 0; kk < 4; ++kk) {
            const int k8 = kk * 8;
            uint32_t a[2][4], b[8][2];
            #pragma unroll
            for (int ma = 0; ma < 2; ++ma) {
                int row = wm * 32 + ma * 16 + g;
                a[ma][0] = As[row * AS_STRIDE + k8 + tg];
                a[ma][1] = As[(row + 8) * AS_STRIDE + k8 + tg];
                a[ma][2] = As[row * AS_STRIDE + k8 + 4 + tg];
                a[ma][3] = As[(row + 8) * AS_STRIDE + k8 + 4 + tg];
            }
            #pragma unroll
            for (int nb = 0; nb < 8; ++nb) {
                int col = wn * 64 + nb * 8 + g;
                b[nb][0] = Bs[(k8 + tg) * BS_STRIDE + col];
                b[nb][1] = Bs[(k8 + 4 + tg) * BS_STRIDE + col];
            }
            #pragma unroll
            for (int ma = 0; ma < 2; ++ma)
                #pragma unroll
                for (int nb = 0; nb < 8; ++nb) {
                    asm volatile(
                        "mma.sync.aligned.m16n8k8.row.col.f32.tf32.tf32.f32 "
                        "{%0,%1,%2,%3},{%4,%5,%6,%7},{%8,%9},{%0,%1,%2,%3};"
                        : "+f"(acc[ma][nb][0]), "+f"(acc[ma][nb][1]),
                          "+f"(acc[ma][nb][2]), "+f"(acc[ma][nb][3])
                        : "r"(a[ma][0]), "r"(a[ma][1]), "r"(a[ma][2]), "r"(a[ma][3]),
                          "r"(b[nb][0]), "r"(b[nb][1]));
                }
        }
        __syncthreads();
    }

    // --- epilogue: bias + (optional) relu, float2 stores
    #pragma unroll
    for (int ma = 0; ma < 2; ++ma) {
        int row0 = bm + wm * 32 + ma * 16 + g;
        #pragma unroll
        for (int nb = 0; nb < 8; ++nb) {
            int col = bn + wn * 64 + nb * 8 + tg * 2;
            float bv0 = bias[col], bv1 = bias[col + 1];
            float2 v0, v1;
            v0.x = acc[ma][nb][0] + bv0;  v0.y = acc[ma][nb][1] + bv1;
            v1.x = acc[ma][nb][2] + bv0;  v1.y = acc[ma][nb][3] + bv1;
            if (RELU) {
                v0.x = fmaxf(v0.x, 0.0f); v0.y = fmaxf(v0.y, 0.0f);
                v1.x = fmaxf(v1.x, 0.0f); v1.y = fmaxf(v1.y, 0.0f);
            }
            *(float2*)(C + (size_t)row0 * N + col)       = v0;
            *(float2*)(C + (size_t)(row0 + 8) * N + col) = v1;
        }
    }
}

// ---------------------------------------------------------------------------
// Kernel 4: out[m] = dot(h2[m,:], W3) + b3  (one warp per row, fp32 exact)
// ---------------------------------------------------------------------------
__global__ void head_kernel(const float* __restrict__ h2,
                            const float* __restrict__ W3,
                            const float* __restrict__ b3,
                            float* __restrict__ out) {
    int wg = (blockIdx.x * blockDim.x + threadIdx.x) >> 5;
    int lane = threadIdx.x & 31;
    if (wg >= M_) return;
    const float* row = h2 + (size_t)wg * N2_;
    float s = 0.0f;
    #pragma unroll
    for (int i = 0; i < N2_ / 128; ++i) {   // 8 iters of float4 per lane
        float4 v = *(const float4*)(row + (i * 32 + lane) * 4);
        float4 w = *(const float4*)(W3  + (i * 32 + lane) * 4);
        s += v.x * w.x + v.y * w.y + v.z * w.z + v.w * w.w;
    }
    #pragma unroll
    for (int o = 16; o; o >>= 1) s += __shfl_xor_sync(0xffffffffu, s, o);
    if (lane == 0) out[wg] = s + b3[0];
}

// ---------------------------------------------------------------------------
extern "C" void kernel_launch(void* const* d_in, const int* in_sizes, int n_in,
                              void* d_out, int out_size) {
    const float* h  = (const float*)d_in[0];
    const float* W1 = (const float*)d_in[1];
    const float* b1 = (const float*)d_in[2];
    const float* W2 = (const float*)d_in[3];
    const float* b2 = (const float*)d_in[4];
    const float* W3 = (const float*)d_in[5];
    const float* b3 = (const float*)d_in[6];
    float* out = (float*)d_out;

    float *feats, *h1, *h2;
    cudaGetSymbolAddress((void**)&feats, g_feats);
    cudaGetSymbolAddress((void**)&h1,    g_h1);
    cudaGetSymbolAddress((void**)&h2,    g_h2);

    // 1) features
    prefix_kernel<<<(B_ * D_ + 255) / 256, 256>>>(h);

    // 2) h1 = relu(feats @ W1 + b1):  [32512,1536] x [1536,2048]
    {
        dim3 grid(M_ / BM, N1_ / BN);
        gemm_tf32<true><<<grid, 256>>>(feats, W1, b1, h1, M_, N1_, K1_);
    }
    // 3) h2 = relu(h1 @ W2 + b2):    [32512,2048] x [2048,1024]
    {
        dim3 grid(M_ / BM, N2_ / BN);
        gemm_tf32<true><<<grid, 256>>>(h1, W2, b2, h2, M_, N2_, K2_);
    }
    // 4) out = h2 @ W3 + b3
    {
        int warps_per_block = 256 / 32;
        int blocks = (M_ + warps_per_block - 1) / warps_per_block;
        head_kernel<<<blocks, 256>>>(h2, W3, b3, out);
    }
}

// round 7
// speedup vs baseline: 2.7174x; 2.7174x over previous
#include <cuda_runtime.h>
#include <cuda_fp16.h>
#include <cstdint>

// ---------------------------------------------------------------- dims
#define B_  128
#define T_  254
#define D_  768
#define H_  1024
#define M_  (B_ * T_)      // 32512
#define K1_ (2 * D_)       // 1536
#define N1_ (2 * H_)       // 2048
#define K2_ N1_            // 2048
#define N2_ H_             // 1024

// ---------------------------------------------------------------- scratch
__device__ __half g_feats[(size_t)M_ * K1_];   // fp16 features [M,1536]
__device__ __half g_h1[(size_t)M_ * N1_];      // fp16 h1 [M,2048]
__device__ float  g_h2[(size_t)M_ * N2_];      // fp32 h2 [M,1024]
__device__ __half g_w1t[(size_t)N1_ * K1_];    // W1^T fp16 [N,K]
__device__ __half g_w2t[(size_t)N2_ * K2_];    // W2^T fp16 [N,K]

// ---------------------------------------------------------------- helpers
__device__ __forceinline__ uint32_t smem_u32(const void* p) {
    uint32_t a;
    asm("{ .reg .u64 t; cvta.to.shared.u64 t, %1; cvt.u32.u64 %0, t; }"
        : "=r"(a) : "l"(p));
    return a;
}

#define CP16(dst, src) \
    asm volatile("cp.async.cg.shared.global [%0], [%1], 16;" \
                 :: "r"(dst), "l"(src) : "memory")

#define LDSM4(r, addr)                                                        \
    asm volatile("ldmatrix.sync.aligned.m8n8.x4.shared.b16 {%0,%1,%2,%3}, [%4];" \
        : "=r"((r)[0]), "=r"((r)[1]), "=r"((r)[2]), "=r"((r)[3]) : "r"(addr))

#define MMA16816(c, a, b0, b1)                                                \
    asm volatile("mma.sync.aligned.m16n8k16.row.col.f32.f16.f16.f32 "         \
        "{%0,%1,%2,%3},{%4,%5,%6,%7},{%8,%9},{%0,%1,%2,%3};"                  \
        : "+f"((c)[0]), "+f"((c)[1]), "+f"((c)[2]), "+f"((c)[3])              \
        : "r"((a)[0]), "r"((a)[1]), "r"((a)[2]), "r"((a)[3]),                 \
          "r"(b0), "r"(b1))

// ---------------------------------------------------------------- kernel: features
__global__ void prefix_kernel(const float* __restrict__ h) {
    int idx = blockIdx.x * blockDim.x + threadIdx.x;
    if (idx >= B_ * D_) return;
    int b = idx / D_;
    int d = idx - b * D_;
    const float* hp = h + (size_t)b * T_ * D_ + d;
    size_t frow = (size_t)b * T_ * K1_ + d;
    float run = 0.0f;
    for (int t = 0; t < T_; ++t) {
        float x = hp[(size_t)t * D_];
        float cnt = (float)(t > 1 ? t : 1);
        g_feats[frow + (size_t)t * K1_]      = __float2half_rn(run / cnt);
        g_feats[frow + (size_t)t * K1_ + D_] = __float2half_rn(x);
        run += x;
    }
}

// ---------------------------------------------------------------- transpose W[K][N] -> half WT[N][K]
__global__ void transpose_cvt(const float* __restrict__ W, __half* __restrict__ WT,
                              int K, int N) {
    __shared__ float tile[32][33];
    int k0 = blockIdx.x * 32, n0 = blockIdx.y * 32;
    int tx = threadIdx.x, ty = threadIdx.y;       // (32, 8)
    #pragma unroll
    for (int j = 0; j < 32; j += 8)
        tile[ty + j][tx] = W[(size_t)(k0 + ty + j) * N + n0 + tx];
    __syncthreads();
    #pragma unroll
    for (int j = 0; j < 32; j += 8)
        WT[(size_t)(n0 + ty + j) * K + k0 + tx] = __float2half_rn(tile[tx][ty + j]);
}

// ---------------------------------------------------------------- fp16 tensor GEMM
// C[M,N] = relu(A[M,K] @ BT[N,K]^T + bias).  A, BT fp16 k-contiguous.
// Tile 128x128, BK=64 halves (128B rows), 3-stage cp.async, ldmatrix, m16n8k16.
#define BM 128
#define BN 128
#define BKH 64
#define STAGES 3
#define A_BYTES (BM * 128)
#define STAGE_BYTES (A_BYTES + BN * 128)      // 32768
#define SMEM_TOTAL (STAGES * STAGE_BYTES)     // 98304

template <bool HALF_OUT>
__global__ __launch_bounds__(256, 2) void gemm_fp16(
    const __half* __restrict__ A, const __half* __restrict__ BT,
    const float* __restrict__ bias, void* __restrict__ Cout,
    int K, int N)
{
    extern __shared__ char smem[];
    const uint32_t sb = smem_u32(smem);
    const int tid = threadIdx.x;
    const int warp = tid >> 5;
    const int lane = tid & 31;
    const int wm = warp & 3;          // 4 warps along M  (32 rows each)
    const int wn = warp >> 2;         // 2 warps along N  (64 cols each)
    const int bm = blockIdx.y * BM;
    const int bn = blockIdx.x * BN;
    const int KC = K / BKH;
    const int lq = lane >> 3;         // quad 0..3
    const int lr = lane & 7;          // row in quad

    float acc[2][8][4];
    #pragma unroll
    for (int i = 0; i < 2; ++i)
        #pragma unroll
        for (int j = 0; j < 8; ++j)
            #pragma unroll
            for (int c = 0; c < 4; ++c) acc[i][j][c] = 0.0f;

    // ---- stage loader: 1024 A-chunks + 1024 B-chunks of 16B, XOR swizzle
    auto load_stage = [&](int q, int s) {
        uint32_t stA = sb + s * STAGE_BYTES;
        uint32_t stB = stA + A_BYTES;
        #pragma unroll
        for (int i = 0; i < 4; ++i) {
            int c = i * 256 + tid;
            int r = c >> 3, col = c & 7;
            const __half* src = A + (size_t)(bm + r) * K + q * BKH + col * 8;
            CP16(stA + r * 128 + ((col ^ (r & 7)) * 16), src);
        }
        #pragma unroll
        for (int i = 0; i < 4; ++i) {
            int c = i * 256 + tid;
            int r = c >> 3, col = c & 7;
            const __half* src = BT + (size_t)(bn + r) * K + q * BKH + col * 8;
            CP16(stB + r * 128 + ((col ^ (r & 7)) * 16), src);
        }
    };

    #pragma unroll
    for (int s = 0; s < STAGES - 1; ++s) {
        load_stage(s, s);
        asm volatile("cp.async.commit_group;" ::: "memory");
    }

    for (int q = 0; q < KC; ++q) {
        asm volatile("cp.async.wait_group %0;" :: "n"(STAGES - 2) : "memory");
        __syncthreads();

        int pre = q + STAGES - 1;
        if (pre < KC) load_stage(pre, pre % STAGES);
        asm volatile("cp.async.commit_group;" ::: "memory");

        uint32_t stA = sb + (q % STAGES) * STAGE_BYTES;
        uint32_t stB = stA + A_BYTES;

        #pragma unroll
        for (int kk = 0; kk < 4; ++kk) {
            uint32_t a[2][4], b[4][4];
            #pragma unroll
            for (int ma = 0; ma < 2; ++ma) {
                // quads 0/1: rows 0-15 @ k-chunk kk*2 ; quads 2/3: same rows @ kk*2+1
                int row = wm * 32 + ma * 16 + (lq & 1) * 8 + lr;
                int ch  = kk * 2 + (lq >> 1);
                LDSM4(a[ma], stA + row * 128 + ((ch ^ (row & 7)) * 16));
            }
            #pragma unroll
            for (int p = 0; p < 4; ++p) {
                // quads 0/1: n rows 0-7 @ chunks kk*2, kk*2+1 ; quads 2/3: n rows 8-15
                int row = wn * 64 + p * 16 + (lq >> 1) * 8 + lr;
                int ch  = kk * 2 + (lq & 1);
                LDSM4(b[p], stB + row * 128 + ((ch ^ (row & 7)) * 16));
            }
            #pragma unroll
            for (int ma = 0; ma < 2; ++ma)
                #pragma unroll
                for (int p = 0; p < 4; ++p) {
                    MMA16816(acc[ma][2 * p],     a[ma], b[p][0], b[p][1]);
                    MMA16816(acc[ma][2 * p + 1], a[ma], b[p][2], b[p][3]);
                }
        }
    }

    // ---- epilogue: bias + relu
    #pragma unroll
    for (int ma = 0; ma < 2; ++ma) {
        int row = bm + wm * 32 + ma * 16 + (lane >> 2);
        #pragma unroll
        for (int nb = 0; nb < 8; ++nb) {
            int col = bn + wn * 64 + nb * 8 + (lane & 3) * 2;
            float bv0 = bias[col], bv1 = bias[col + 1];
            float v0 = fmaxf(acc[ma][nb][0] + bv0, 0.0f);
            float v1 = fmaxf(acc[ma][nb][1] + bv1, 0.0f);
            float v2 = fmaxf(acc[ma][nb][2] + bv0, 0.0f);
            float v3 = fmaxf(acc[ma][nb][3] + bv1, 0.0f);
            if (HALF_OUT) {
                __half* C = (__half*)Cout;
                *(__half2*)(C + (size_t)row * N + col)       = __floats2half2_rn(v0, v1);
                *(__half2*)(C + (size_t)(row + 8) * N + col) = __floats2half2_rn(v2, v3);
            } else {
                float* C = (float*)Cout;
                float2 w0 = {v0, v1}, w1 = {v2, v3};
                *(float2*)(C + (size_t)row * N + col)       = w0;
                *(float2*)(C + (size_t)(row + 8) * N + col) = w1;
            }
        }
    }
}

// ---------------------------------------------------------------- head
__global__ void head_kernel(const float* __restrict__ h2,
                            const float* __restrict__ W3,
                            const float* __restrict__ b3,
                            float* __restrict__ out) {
    int wg = (blockIdx.x * blockDim.x + threadIdx.x) >> 5;
    int lane = threadIdx.x & 31;
    if (wg >= M_) return;
    const float* row = h2 + (size_t)wg * N2_;
    float s = 0.0f;
    #pragma unroll
    for (int i = 0; i < N2_ / 128; ++i) {
        float4 v = *(const float4*)(row + (i * 32 + lane) * 4);
        float4 w = *(const float4*)(W3  + (i * 32 + lane) * 4);
        s += v.x * w.x + v.y * w.y + v.z * w.z + v.w * w.w;
    }
    #pragma unroll
    for (int o = 16; o; o >>= 1) s += __shfl_xor_sync(0xffffffffu, s, o);
    if (lane == 0) out[wg] = s + b3[0];
}

// Tiny no-op launches so ncu's "-s 5 -c 1" lands on GEMM1 (launch index 5).
__global__ void noop_kernel() {}

// ---------------------------------------------------------------- launcher
extern "C" void kernel_launch(void* const* d_in, const int* in_sizes, int n_in,
                              void* d_out, int out_size) {
    const float* h  = (const float*)d_in[0];
    const float* W1 = (const float*)d_in[1];
    const float* b1 = (const float*)d_in[2];
    const float* W2 = (const float*)d_in[3];
    const float* b2 = (const float*)d_in[4];
    const float* W3 = (const float*)d_in[5];
    const float* b3 = (const float*)d_in[6];
    float* out = (float*)d_out;

    __half *feats, *h1, *w1t, *w2t;
    float *h2;
    cudaGetSymbolAddress((void**)&feats, g_feats);
    cudaGetSymbolAddress((void**)&h1,    g_h1);
    cudaGetSymbolAddress((void**)&h2,    g_h2);
    cudaGetSymbolAddress((void**)&w1t,   g_w1t);
    cudaGetSymbolAddress((void**)&w2t,   g_w2t);

    cudaFuncSetAttribute(gemm_fp16<true>,
        cudaFuncAttributeMaxDynamicSharedMemorySize, SMEM_TOTAL);
    cudaFuncSetAttribute(gemm_fp16<false>,
        cudaFuncAttributeMaxDynamicSharedMemorySize, SMEM_TOTAL);

    // launch 0,1: weight transposes (fp16)
    {
        dim3 blk(32, 8);
        transpose_cvt<<<dim3(K1_ / 32, N1_ / 32), blk>>>(W1, w1t, K1_, N1_);
        transpose_cvt<<<dim3(K2_ / 32, N2_ / 32), blk>>>(W2, w2t, K2_, N2_);
    }
    // launch 2: features (fp16)
    prefix_kernel<<<(B_ * D_ + 255) / 256, 256>>>(h);
    // launches 3,4: no-ops (ncu alignment)
    noop_kernel<<<1, 32>>>();
    noop_kernel<<<1, 32>>>();

    // launch 5: h1 = relu(feats @ W1 + b1)  [32512,1536]x[1536,2048] -> fp16
    gemm_fp16<true><<<dim3(N1_ / BN, M_ / BM), 256, SMEM_TOTAL>>>(
        feats, w1t, b1, h1, K1_, N1_);

    // launch 6: h2 = relu(h1 @ W2 + b2)     [32512,2048]x[2048,1024] -> fp32
    gemm_fp16<false><<<dim3(N2_ / BN, M_ / BM), 256, SMEM_TOTAL>>>(
        h1, w2t, b2, h2, K2_, N2_);

    // launch 7: out = h2 @ W3 + b3
    head_kernel<<<(M_ * 32 + 255) / 256, 256>>>(h2, W3, b3, out);
}

// round 8
// speedup vs baseline: 2.8329x; 1.0425x over previous
#include <cuda_runtime.h>
#include <cuda_fp16.h>
#include <cstdint>

// ---------------------------------------------------------------- dims
#define B_  128
#define T_  254
#define D_  768
#define H_  1024
#define M_  (B_ * T_)      // 32512
#define K1_ (2 * D_)       // 1536
#define N1_ (2 * H_)       // 2048
#define K2_ N1_            // 2048
#define N2_ H_             // 1024

// ---------------------------------------------------------------- scratch
__device__ __half g_feats[(size_t)M_ * K1_];   // fp16 features [M,1536]
__device__ __half g_h1[(size_t)M_ * N1_];      // fp16 h1 [M,2048]
__device__ __half g_w1t[(size_t)N1_ * K1_];    // W1^T fp16 [N,K]
__device__ __half g_w2t[(size_t)N2_ * K2_];    // W2^T fp16 [N,K]

// ---------------------------------------------------------------- helpers
__device__ __forceinline__ uint32_t smem_u32(const void* p) {
    uint32_t a;
    asm("{ .reg .u64 t; cvta.to.shared.u64 t, %1; cvt.u32.u64 %0, t; }"
        : "=r"(a) : "l"(p));
    return a;
}

#define CP16(dst, src) \
    asm volatile("cp.async.cg.shared.global [%0], [%1], 16;" \
                 :: "r"(dst), "l"(src) : "memory")

#define LDSM4(r, addr)                                                        \
    asm volatile("ldmatrix.sync.aligned.m8n8.x4.shared.b16 {%0,%1,%2,%3}, [%4];" \
        : "=r"((r)[0]), "=r"((r)[1]), "=r"((r)[2]), "=r"((r)[3]) : "r"(addr))

#define MMA16816(c, a, b0, b1)                                                \
    asm volatile("mma.sync.aligned.m16n8k16.row.col.f32.f16.f16.f32 "         \
        "{%0,%1,%2,%3},{%4,%5,%6,%7},{%8,%9},{%0,%1,%2,%3};"                  \
        : "+f"((c)[0]), "+f"((c)[1]), "+f"((c)[2]), "+f"((c)[3])              \
        : "r"((a)[0]), "r"((a)[1]), "r"((a)[2]), "r"((a)[3]),                 \
          "r"(b0), "r"(b1))

// ---------------------------------------------------------------- kernel: features
// Each thread handles TWO adjacent d's -> __half2 stores (full-width transactions).
__global__ void prefix_kernel(const float* __restrict__ h) {
    int idx = blockIdx.x * blockDim.x + threadIdx.x;   // over B_*D_/2
    if (idx >= B_ * D_ / 2) return;
    int b  = idx / (D_ / 2);
    int d2 = idx - b * (D_ / 2);
    const float2* hp = (const float2*)(h + (size_t)b * T_ * D_) + d2;
    __half2* fm = (__half2*)(g_feats + (size_t)b * T_ * K1_) + d2;          // mean half
    __half2* fx = (__half2*)(g_feats + (size_t)b * T_ * K1_ + D_) + d2;     // token half
    float r0 = 0.0f, r1 = 0.0f;
    for (int t = 0; t < T_; ++t) {
        float2 x = hp[(size_t)t * (D_ / 2)];
        float inv = 1.0f / (float)(t > 1 ? t : 1);
        fm[(size_t)t * (K1_ / 2)] = __floats2half2_rn(r0 * inv, r1 * inv);
        fx[(size_t)t * (K1_ / 2)] = __floats2half2_rn(x.x, x.y);
        r0 += x.x; r1 += x.y;
    }
}

// ---------------------------------------------------------------- transpose W[K][N] -> half WT[N][K]
__global__ void transpose_cvt(const float* __restrict__ W, __half* __restrict__ WT,
                              int K, int N) {
    __shared__ float tile[32][33];
    int k0 = blockIdx.x * 32, n0 = blockIdx.y * 32;
    int tx = threadIdx.x, ty = threadIdx.y;       // (32, 8)
    #pragma unroll
    for (int j = 0; j < 32; j += 8)
        tile[ty + j][tx] = W[(size_t)(k0 + ty + j) * N + n0 + tx];
    __syncthreads();
    #pragma unroll
    for (int j = 0; j < 32; j += 8)
        WT[(size_t)(n0 + ty + j) * K + k0 + tx] = __float2half_rn(tile[tx][ty + j]);
}

// ---------------------------------------------------------------- out = b3
__global__ void init_out(float* __restrict__ out, const float* __restrict__ b3) {
    int i = blockIdx.x * blockDim.x + threadIdx.x;
    if (i < M_) out[i] = b3[0];
}

// ---------------------------------------------------------------- fp16 tensor GEMM
// FUSE_HEAD=false: C[M,N] = relu(A @ BT^T + bias)   (fp16 store)
// FUSE_HEAD=true : out[m] += sum_n relu(A@BT^T+bias)[m,n] * W3[n]  (atomicAdd)
#define BM 128
#define BN 128
#define BKH 64
#define STAGES 3
#define A_BYTES (BM * 128)
#define STAGE_BYTES (A_BYTES + BN * 128)      // 32768
#define SMEM_TOTAL (STAGES * STAGE_BYTES)     // 98304

template <bool FUSE_HEAD>
__global__ __launch_bounds__(256, 2) void gemm_fp16(
    const __half* __restrict__ A, const __half* __restrict__ BT,
    const float* __restrict__ bias, __half* __restrict__ C,
    const float* __restrict__ W3, float* __restrict__ out,
    int K, int N)
{
    extern __shared__ char smem[];
    const uint32_t sb = smem_u32(smem);
    const int tid = threadIdx.x;
    const int warp = tid >> 5;
    const int lane = tid & 31;
    const int wm = warp & 3;          // 4 warps along M  (32 rows each)
    const int wn = warp >> 2;         // 2 warps along N  (64 cols each)
    const int bm = blockIdx.y * BM;
    const int bn = blockIdx.x * BN;
    const int KC = K / BKH;
    const int lq = lane >> 3;         // quad 0..3
    const int lr = lane & 7;          // row in quad

    float acc[2][8][4];
    #pragma unroll
    for (int i = 0; i < 2; ++i)
        #pragma unroll
        for (int j = 0; j < 8; ++j)
            #pragma unroll
            for (int c = 0; c < 4; ++c) acc[i][j][c] = 0.0f;

    auto load_stage = [&](int q, int s) {
        uint32_t stA = sb + s * STAGE_BYTES;
        uint32_t stB = stA + A_BYTES;
        #pragma unroll
        for (int i = 0; i < 4; ++i) {
            int c = i * 256 + tid;
            int r = c >> 3, col = c & 7;
            const __half* src = A + (size_t)(bm + r) * K + q * BKH + col * 8;
            CP16(stA + r * 128 + ((col ^ (r & 7)) * 16), src);
        }
        #pragma unroll
        for (int i = 0; i < 4; ++i) {
            int c = i * 256 + tid;
            int r = c >> 3, col = c & 7;
            const __half* src = BT + (size_t)(bn + r) * K + q * BKH + col * 8;
            CP16(stB + r * 128 + ((col ^ (r & 7)) * 16), src);
        }
    };

    #pragma unroll
    for (int s = 0; s < STAGES - 1; ++s) {
        load_stage(s, s);
        asm volatile("cp.async.commit_group;" ::: "memory");
    }

    for (int q = 0; q < KC; ++q) {
        asm volatile("cp.async.wait_group %0;" :: "n"(STAGES - 2) : "memory");
        __syncthreads();

        int pre = q + STAGES - 1;
        if (pre < KC) load_stage(pre, pre % STAGES);
        asm volatile("cp.async.commit_group;" ::: "memory");

        uint32_t stA = sb + (q % STAGES) * STAGE_BYTES;
        uint32_t stB = stA + A_BYTES;

        #pragma unroll
        for (int kk = 0; kk < 4; ++kk) {
            uint32_t a[2][4], b[4][4];
            #pragma unroll
            for (int ma = 0; ma < 2; ++ma) {
                int row = wm * 32 + ma * 16 + (lq & 1) * 8 + lr;
                int ch  = kk * 2 + (lq >> 1);
                LDSM4(a[ma], stA + row * 128 + ((ch ^ (row & 7)) * 16));
            }
            #pragma unroll
            for (int p = 0; p < 4; ++p) {
                int row = wn * 64 + p * 16 + (lq >> 1) * 8 + lr;
                int ch  = kk * 2 + (lq & 1);
                LDSM4(b[p], stB + row * 128 + ((ch ^ (row & 7)) * 16));
            }
            #pragma unroll
            for (int ma = 0; ma < 2; ++ma)
                #pragma unroll
                for (int p = 0; p < 4; ++p) {
                    MMA16816(acc[ma][2 * p],     a[ma], b[p][0], b[p][1]);
                    MMA16816(acc[ma][2 * p + 1], a[ma], b[p][2], b[p][3]);
                }
        }
    }

    if (!FUSE_HEAD) {
        // ---- epilogue: bias + relu -> fp16 store
        #pragma unroll
        for (int ma = 0; ma < 2; ++ma) {
            int row = bm + wm * 32 + ma * 16 + (lane >> 2);
            #pragma unroll
            for (int nb = 0; nb < 8; ++nb) {
                int col = bn + wn * 64 + nb * 8 + (lane & 3) * 2;
                float bv0 = bias[col], bv1 = bias[col + 1];
                float v0 = fmaxf(acc[ma][nb][0] + bv0, 0.0f);
                float v1 = fmaxf(acc[ma][nb][1] + bv1, 0.0f);
                float v2 = fmaxf(acc[ma][nb][2] + bv0, 0.0f);
                float v3 = fmaxf(acc[ma][nb][3] + bv1, 0.0f);
                *(__half2*)(C + (size_t)row * N + col)       = __floats2half2_rn(v0, v1);
                *(__half2*)(C + (size_t)(row + 8) * N + col) = __floats2half2_rn(v2, v3);
            }
        }
    } else {
        // ---- epilogue: out[m] += dot(relu(acc+bias), W3)  (no C tensor at all)
        float p0 = 0.f, p1 = 0.f, p2 = 0.f, p3 = 0.f;
        #pragma unroll
        for (int nb = 0; nb < 8; ++nb) {
            int col = bn + wn * 64 + nb * 8 + (lane & 3) * 2;
            float bv0 = bias[col], bv1 = bias[col + 1];
            float w0 = W3[col],    w1 = W3[col + 1];
            p0 += fmaxf(acc[0][nb][0] + bv0, 0.f) * w0 + fmaxf(acc[0][nb][1] + bv1, 0.f) * w1;
            p1 += fmaxf(acc[0][nb][2] + bv0, 0.f) * w0 + fmaxf(acc[0][nb][3] + bv1, 0.f) * w1;
            p2 += fmaxf(acc[1][nb][0] + bv0, 0.f) * w0 + fmaxf(acc[1][nb][1] + bv1, 0.f) * w1;
            p3 += fmaxf(acc[1][nb][2] + bv0, 0.f) * w0 + fmaxf(acc[1][nb][3] + bv1, 0.f) * w1;
        }
        // reduce over the 4 lanes (lane&3) sharing each row
        #pragma unroll
        for (int o = 1; o <= 2; o <<= 1) {
            p0 += __shfl_xor_sync(0xffffffffu, p0, o);
            p1 += __shfl_xor_sync(0xffffffffu, p1, o);
            p2 += __shfl_xor_sync(0xffffffffu, p2, o);
            p3 += __shfl_xor_sync(0xffffffffu, p3, o);
        }
        __syncthreads();                 // mainloop smem dead -> reuse as red buffer
        float* red = (float*)smem;       // [2][128]
        if ((lane & 3) == 0) {
            int rl = wm * 32 + (lane >> 2);
            red[wn * 128 + rl]      = p0;
            red[wn * 128 + rl + 8]  = p1;
            red[wn * 128 + rl + 16] = p2;
            red[wn * 128 + rl + 24] = p3;
        }
        __syncthreads();
        if (tid < 128)
            atomicAdd(&out[bm + tid], red[tid] + red[128 + tid]);
    }
}

// ---------------------------------------------------------------- launcher
extern "C" void kernel_launch(void* const* d_in, const int* in_sizes, int n_in,
                              void* d_out, int out_size) {
    const float* h  = (const float*)d_in[0];
    const float* W1 = (const float*)d_in[1];
    const float* b1 = (const float*)d_in[2];
    const float* W2 = (const float*)d_in[3];
    const float* b2 = (const float*)d_in[4];
    const float* W3 = (const float*)d_in[5];
    const float* b3 = (const float*)d_in[6];
    float* out = (float*)d_out;

    __half *feats, *h1, *w1t, *w2t;
    cudaGetSymbolAddress((void**)&feats, g_feats);
    cudaGetSymbolAddress((void**)&h1,    g_h1);
    cudaGetSymbolAddress((void**)&w1t,   g_w1t);
    cudaGetSymbolAddress((void**)&w2t,   g_w2t);

    cudaFuncSetAttribute(gemm_fp16<false>,
        cudaFuncAttributeMaxDynamicSharedMemorySize, SMEM_TOTAL);
    cudaFuncSetAttribute(gemm_fp16<true>,
        cudaFuncAttributeMaxDynamicSharedMemorySize, SMEM_TOTAL);

    // launch 0,1: weight transposes (fp16)
    {
        dim3 blk(32, 8);
        transpose_cvt<<<dim3(K1_ / 32, N1_ / 32), blk>>>(W1, w1t, K1_, N1_);
        transpose_cvt<<<dim3(K2_ / 32, N2_ / 32), blk>>>(W2, w2t, K2_, N2_);
    }
    // launch 2: features (fp16, half2 stores)
    prefix_kernel<<<(B_ * D_ / 2 + 255) / 256, 256>>>(h);
    // launch 3: out = b3
    init_out<<<(M_ + 255) / 256, 256>>>(out, b3);

    // launch 4: h1 = relu(feats @ W1 + b1)  -> fp16
    gemm_fp16<false><<<dim3(N1_ / BN, M_ / BM), 256, SMEM_TOTAL>>>(
        feats, w1t, b1, h1, nullptr, nullptr, K1_, N1_);

    // launch 5: out += relu(h1 @ W2 + b2) @ W3   (head fused, no h2 tensor)
    gemm_fp16<true><<<dim3(N2_ / BN, M_ / BM), 256, SMEM_TOTAL>>>(
        h1, w2t, b2, nullptr, W3, out, K2_, N2_);
}

// round 10
// speedup vs baseline: 2.9848x; 1.0536x over previous
#include <cuda_runtime.h>
#include <cuda_fp16.h>
#include <cstdint>

// ---------------------------------------------------------------- dims
#define B_  128
#define T_  254
#define D_  768
#define H_  1024
#define M_  (B_ * T_)      // 32512
#define K1_ (2 * D_)       // 1536
#define N1_ (2 * H_)       // 2048
#define K2_ N1_            // 2048
#define N2_ H_             // 1024

// ---------------------------------------------------------------- scratch
__device__ __half g_feats[(size_t)M_ * K1_];   // fp16 features [M,1536]
__device__ __half g_h1[(size_t)M_ * N1_];      // fp16 h1 [M,2048]
__device__ __half g_w1t[(size_t)N1_ * K1_];    // W1^T fp16 [N,K]
__device__ __half g_w2t[(size_t)N2_ * K2_];    // W2^T fp16 [N,K]

// ---------------------------------------------------------------- helpers
__device__ __forceinline__ uint32_t smem_u32(const void* p) {
    uint32_t a;
    asm("{ .reg .u64 t; cvta.to.shared.u64 t, %1; cvt.u32.u64 %0, t; }"
        : "=r"(a) : "l"(p));
    return a;
}

#define CP16(dst, src) \
    asm volatile("cp.async.cg.shared.global [%0], [%1], 16;" \
                 :: "r"(dst), "l"(src) : "memory")

#define LDSM4(r, addr)                                                        \
    asm volatile("ldmatrix.sync.aligned.m8n8.x4.shared.b16 {%0,%1,%2,%3}, [%4];" \
        : "=r"((r)[0]), "=r"((r)[1]), "=r"((r)[2]), "=r"((r)[3]) : "r"(addr))

#define MMA16816(c, a, b0, b1)                                                \
    asm volatile("mma.sync.aligned.m16n8k16.row.col.f32.f16.f16.f32 "         \
        "{%0,%1,%2,%3},{%4,%5,%6,%7},{%8,%9},{%0,%1,%2,%3};"                  \
        : "+f"((c)[0]), "+f"((c)[1]), "+f"((c)[2]), "+f"((c)[3])              \
        : "r"((a)[0]), "r"((a)[1]), "r"((a)[2]), "r"((a)[3]),                 \
          "r"(b0), "r"(b1))

// ---------------------------------------------------------------- fused setup
// One kernel, range-partitioned grid:
//   [0, 192)            prefix scan -> g_feats      (long blocks, scheduled first)
//   [192, 192+3072)     transpose W1 -> g_w1t
//   [.., +2048)         transpose W2 -> g_w2t
//   [.., +127)          out = b3
#define PFX_BLKS  (B_ * D_ / 2 / 256)                  // 192
#define T1_BX     (K1_ / 32)                           // 48
#define T1_BLKS   (T1_BX * (N1_ / 32))                 // 3072
#define T2_BX     (K2_ / 32)                           // 64
#define T2_BLKS   (T2_BX * (N2_ / 32))                 // 2048
#define INIT_BLKS ((M_ + 255) / 256)                   // 127
#define SETUP_BLKS (PFX_BLKS + T1_BLKS + T2_BLKS + INIT_BLKS)

__device__ __forceinline__ void do_transpose(const float* __restrict__ W,
                                             __half* __restrict__ WT,
                                             int K, int N, int bx, int by, int tid) {
    __shared__ float tile[32][33];
    int k0 = bx * 32, n0 = by * 32;
    int tx = tid & 31, ty = tid >> 5;                  // (32, 8)
    #pragma unroll
    for (int j = 0; j < 32; j += 8)
        tile[ty + j][tx] = W[(size_t)(k0 + ty + j) * N + n0 + tx];
    __syncthreads();
    #pragma unroll
    for (int j = 0; j < 32; j += 8)
        WT[(size_t)(n0 + ty + j) * K + k0 + tx] = __float2half_rn(tile[tx][ty + j]);
}

__global__ __launch_bounds__(256) void setup_kernel(
    const float* __restrict__ h,
    const float* __restrict__ W1, const float* __restrict__ W2,
    const float* __restrict__ b3, float* __restrict__ out)
{
    int blk = blockIdx.x;
    int tid = threadIdx.x;

    if (blk < PFX_BLKS) {
        // ---- prefix mean + token copy, t-loop unrolled x4 for MLP
        int idx = blk * 256 + tid;                     // over B_*D_/2
        int b  = idx / (D_ / 2);
        int d2 = idx - b * (D_ / 2);
        const float2* hp = (const float2*)(h + (size_t)b * T_ * D_) + d2;
        __half2* fm = (__half2*)(g_feats + (size_t)b * T_ * K1_) + d2;
        __half2* fx = (__half2*)(g_feats + (size_t)b * T_ * K1_ + D_) + d2;
        float r0 = 0.0f, r1 = 0.0f;
        int t = 0;
        #pragma unroll 1
        for (; t + 4 <= T_; t += 4) {
            float2 x0 = hp[(size_t)(t + 0) * (D_ / 2)];
            float2 x1 = hp[(size_t)(t + 1) * (D_ / 2)];
            float2 x2 = hp[(size_t)(t + 2) * (D_ / 2)];
            float2 x3 = hp[(size_t)(t + 3) * (D_ / 2)];
            float i0 = 1.0f / (float)(t + 0 > 1 ? t + 0 : 1);
            float i1 = 1.0f / (float)(t + 1);
            float i2 = 1.0f / (float)(t + 2);
            float i3 = 1.0f / (float)(t + 3);
            fm[(size_t)(t + 0) * (K1_ / 2)] = __floats2half2_rn(r0 * i0, r1 * i0);
            fx[(size_t)(t + 0) * (K1_ / 2)] = __floats2half2_rn(x0.x, x0.y);
            r0 += x0.x; r1 += x0.y;
            fm[(size_t)(t + 1) * (K1_ / 2)] = __floats2half2_rn(r0 * i1, r1 * i1);
            fx[(size_t)(t + 1) * (K1_ / 2)] = __floats2half2_rn(x1.x, x1.y);
            r0 += x1.x; r1 += x1.y;
            fm[(size_t)(t + 2) * (K1_ / 2)] = __floats2half2_rn(r0 * i2, r1 * i2);
            fx[(size_t)(t + 2) * (K1_ / 2)] = __floats2half2_rn(x2.x, x2.y);
            r0 += x2.x; r1 += x2.y;
            fm[(size_t)(t + 3) * (K1_ / 2)] = __floats2half2_rn(r0 * i3, r1 * i3);
            fx[(size_t)(t + 3) * (K1_ / 2)] = __floats2half2_rn(x3.x, x3.y);
            r0 += x3.x; r1 += x3.y;
        }
        for (; t < T_; ++t) {
            float2 x = hp[(size_t)t * (D_ / 2)];
            float inv = 1.0f / (float)(t > 1 ? t : 1);
            fm[(size_t)t * (K1_ / 2)] = __floats2half2_rn(r0 * inv, r1 * inv);
            fx[(size_t)t * (K1_ / 2)] = __floats2half2_rn(x.x, x.y);
            r0 += x.x; r1 += x.y;
        }
    } else if (blk < PFX_BLKS + T1_BLKS) {
        int t = blk - PFX_BLKS;
        do_transpose(W1, g_w1t, K1_, N1_, t % T1_BX, t / T1_BX, tid);
    } else if (blk < PFX_BLKS + T1_BLKS + T2_BLKS) {
        int t = blk - PFX_BLKS - T1_BLKS;
        do_transpose(W2, g_w2t, K2_, N2_, t % T2_BX, t / T2_BX, tid);
    } else {
        int i = (blk - PFX_BLKS - T1_BLKS - T2_BLKS) * 256 + tid;
        if (i < M_) out[i] = b3[0];
    }
}

// ---------------------------------------------------------------- fp16 tensor GEMM
// FUSE_HEAD=false: C[M,N] = relu(A @ BT^T + bias)   (fp16 store)
// FUSE_HEAD=true : out[m] += sum_n relu(A@BT^T+bias)[m,n] * W3[n]  (atomicAdd)
#define BM 128
#define BN 128
#define BKH 64
#define STAGES 3
#define A_BYTES (BM * 128)
#define STAGE_BYTES (A_BYTES + BN * 128)      // 32768
#define SMEM_TOTAL (STAGES * STAGE_BYTES)     // 98304

template <bool FUSE_HEAD>
__global__ __launch_bounds__(256, 2) void gemm_fp16(
    const __half* __restrict__ A, const __half* __restrict__ BT,
    const float* __restrict__ bias, __half* __restrict__ C,
    const float* __restrict__ W3, float* __restrict__ out,
    int K, int N)
{
    extern __shared__ char smem[];
    const uint32_t sb = smem_u32(smem);
    const int tid = threadIdx.x;
    const int warp = tid >> 5;
    const int lane = tid & 31;
    const int wm = warp & 3;          // 4 warps along M  (32 rows each)
    const int wn = warp >> 2;         // 2 warps along N  (64 cols each)
    const int bm = blockIdx.y * BM;
    const int bn = blockIdx.x * BN;
    const int KC = K / BKH;
    const int lq = lane >> 3;         // quad 0..3
    const int lr = lane & 7;          // row in quad

    float acc[2][8][4];
    #pragma unroll
    for (int i = 0; i < 2; ++i)
        #pragma unroll
        for (int j = 0; j < 8; ++j)
            #pragma unroll
            for (int c = 0; c < 4; ++c) acc[i][j][c] = 0.0f;

    auto load_stage = [&](int q, int s) {
        uint32_t stA = sb + s * STAGE_BYTES;
        uint32_t stB = stA + A_BYTES;
        #pragma unroll
        for (int i = 0; i < 4; ++i) {
            int c = i * 256 + tid;
            int r = c >> 3, col = c & 7;
            const __half* src = A + (size_t)(bm + r) * K + q * BKH + col * 8;
            CP16(stA + r * 128 + ((col ^ (r & 7)) * 16), src);
        }
        #pragma unroll
        for (int i = 0; i < 4; ++i) {
            int c = i * 256 + tid;
            int r = c >> 3, col = c & 7;
            const __half* src = BT + (size_t)(bn + r) * K + q * BKH + col * 8;
            CP16(stB + r * 128 + ((col ^ (r & 7)) * 16), src);
        }
    };

    #pragma unroll
    for (int s = 0; s < STAGES - 1; ++s) {
        load_stage(s, s);
        asm volatile("cp.async.commit_group;" ::: "memory");
    }

    for (int q = 0; q < KC; ++q) {
        asm volatile("cp.async.wait_group %0;" :: "n"(STAGES - 2) : "memory");
        __syncthreads();

        int pre = q + STAGES - 1;
        if (pre < KC) load_stage(pre, pre % STAGES);
        asm volatile("cp.async.commit_group;" ::: "memory");

        uint32_t stA = sb + (q % STAGES) * STAGE_BYTES;
        uint32_t stB = stA + A_BYTES;

        #pragma unroll
        for (int kk = 0; kk < 4; ++kk) {
            uint32_t a[2][4], b[4][4];
            #pragma unroll
            for (int ma = 0; ma < 2; ++ma) {
                int row = wm * 32 + ma * 16 + (lq & 1) * 8 + lr;
                int ch  = kk * 2 + (lq >> 1);
                LDSM4(a[ma], stA + row * 128 + ((ch ^ (row & 7)) * 16));
            }
            #pragma unroll
            for (int p = 0; p < 4; ++p) {
                int row = wn * 64 + p * 16 + (lq >> 1) * 8 + lr;
                int ch  = kk * 2 + (lq & 1);
                LDSM4(b[p], stB + row * 128 + ((ch ^ (row & 7)) * 16));
            }
            #pragma unroll
            for (int ma = 0; ma < 2; ++ma)
                #pragma unroll
                for (int p = 0; p < 4; ++p) {
                    MMA16816(acc[ma][2 * p],     a[ma], b[p][0], b[p][1]);
                    MMA16816(acc[ma][2 * p + 1], a[ma], b[p][2], b[p][3]);
                }
        }
    }

    if (!FUSE_HEAD) {
        // ---- epilogue: bias + relu -> fp16 store
        #pragma unroll
        for (int ma = 0; ma < 2; ++ma) {
            int row = bm + wm * 32 + ma * 16 + (lane >> 2);
            #pragma unroll
            for (int nb = 0; nb < 8; ++nb) {
                int col = bn + wn * 64 + nb * 8 + (lane & 3) * 2;
                float bv0 = bias[col], bv1 = bias[col + 1];
                float v0 = fmaxf(acc[ma][nb][0] + bv0, 0.0f);
                float v1 = fmaxf(acc[ma][nb][1] + bv1, 0.0f);
                float v2 = fmaxf(acc[ma][nb][2] + bv0, 0.0f);
                float v3 = fmaxf(acc[ma][nb][3] + bv1, 0.0f);
                *(__half2*)(C + (size_t)row * N + col)       = __floats2half2_rn(v0, v1);
                *(__half2*)(C + (size_t)(row + 8) * N + col) = __floats2half2_rn(v2, v3);
            }
        }
    } else {
        // ---- epilogue: out[m] += dot(relu(acc+bias), W3)  (no C tensor at all)
        float p0 = 0.f, p1 = 0.f, p2 = 0.f, p3 = 0.f;
        #pragma unroll
        for (int nb = 0; nb < 8; ++nb) {
            int col = bn + wn * 64 + nb * 8 + (lane & 3) * 2;
            float bv0 = bias[col], bv1 = bias[col + 1];
            float w0 = W3[col],    w1 = W3[col + 1];
            p0 += fmaxf(acc[0][nb][0] + bv0, 0.f) * w0 + fmaxf(acc[0][nb][1] + bv1, 0.f) * w1;
            p1 += fmaxf(acc[0][nb][2] + bv0, 0.f) * w0 + fmaxf(acc[0][nb][3] + bv1, 0.f) * w1;
            p2 += fmaxf(acc[1][nb][0] + bv0, 0.f) * w0 + fmaxf(acc[1][nb][1] + bv1, 0.f) * w1;
            p3 += fmaxf(acc[1][nb][2] + bv0, 0.f) * w0 + fmaxf(acc[1][nb][3] + bv1, 0.f) * w1;
        }
        #pragma unroll
        for (int o = 1; o <= 2; o <<= 1) {
            p0 += __shfl_xor_sync(0xffffffffu, p0, o);
            p1 += __shfl_xor_sync(0xffffffffu, p1, o);
            p2 += __shfl_xor_sync(0xffffffffu, p2, o);
            p3 += __shfl_xor_sync(0xffffffffu, p3, o);
        }
        __syncthreads();                 // mainloop smem dead -> reuse as red buffer
        float* red = (float*)smem;       // [2][128]
        if ((lane & 3) == 0) {
            int rl = wm * 32 + (lane >> 2);
            red[wn * 128 + rl]      = p0;
            red[wn * 128 + rl + 8]  = p1;
            red[wn * 128 + rl + 16] = p2;
            red[wn * 128 + rl + 24] = p3;
        }
        __syncthreads();
        if (tid < 128)
            atomicAdd(&out[bm + tid], red[tid] + red[128 + tid]);
    }
}

// ---------------------------------------------------------------- launcher
extern "C" void kernel_launch(void* const* d_in, const int* in_sizes, int n_in,
                              void* d_out, int out_size) {
    const float* h  = (const float*)d_in[0];
    const float* W1 = (const float*)d_in[1];
    const float* b1 = (const float*)d_in[2];
    const float* W2 = (const float*)d_in[3];
    const float* b2 = (const float*)d_in[4];
    const float* W3 = (const float*)d_in[5];
    const float* b3 = (const float*)d_in[6];
    float* out = (float*)d_out;

    __half *feats, *h1, *w1t, *w2t;
    cudaGetSymbolAddress((void**)&feats, g_feats);
    cudaGetSymbolAddress((void**)&h1,    g_h1);
    cudaGetSymbolAddress((void**)&w1t,   g_w1t);
    cudaGetSymbolAddress((void**)&w2t,   g_w2t);

    cudaFuncSetAttribute(gemm_fp16<false>,
        cudaFuncAttributeMaxDynamicSharedMemorySize, SMEM_TOTAL);
    cudaFuncSetAttribute(gemm_fp16<true>,
        cudaFuncAttributeMaxDynamicSharedMemorySize, SMEM_TOTAL);

    // launch 0: fused setup (prefix + both transposes + out=b3, overlapped)
    setup_kernel<<<SETUP_BLKS, 256>>>(h, W1, W2, b3, out);

    // launch 1: h1 = relu(feats @ W1 + b1)  -> fp16
    gemm_fp16<false><<<dim3(N1_ / BN, M_ / BM), 256, SMEM_TOTAL>>>(
        feats, w1t, b1, h1, nullptr, nullptr, K1_, N1_);

    // launch 2: out += relu(h1 @ W2 + b2) @ W3   (head fused, no h2 tensor)
    gemm_fp16<true><<<dim3(N2_ / BN, M_ / BM), 256, SMEM_TOTAL>>>(
        h1, w2t, b2, nullptr, W3, out, K2_, N2_);
}